// round 3
// baseline (speedup 1.0000x reference)
#include <cuda_runtime.h>

#define NTOK 16384
#define DIN  512
#define DOUT 512
#define NB   8
#define KK   4608          // DIN * 9 (relu + 8 spline features per input dim)
#define NKT  288           // KK / 16

// Scratch (allocation-free per harness rules)
__device__ __align__(16) float g_F[(size_t)NTOK * KK];   // features [tok][k]
__device__ __align__(16) float g_W[(size_t)KK * DOUT];   // packed weights [k][o]

// ---------------------------------------------------------------------------
// Kernel 1: LayerNorm + feature generation.
// One block per token, 512 threads (one per input dim).
// ---------------------------------------------------------------------------
__global__ __launch_bounds__(512)
void feat_kernel(const float* __restrict__ x,
                 const float* __restrict__ gamma_,
                 const float* __restrict__ beta_)
{
    const int tok = blockIdx.x;
    const int d   = threadIdx.x;
    const float v = x[(size_t)tok * DIN + d];

    __shared__ float red[16];

    // ---- mean ----
    float s = v;
    #pragma unroll
    for (int o = 16; o > 0; o >>= 1) s += __shfl_xor_sync(0xffffffffu, s, o);
    if ((d & 31) == 0) red[d >> 5] = s;
    __syncthreads();
    if (d < 16) {
        float t = red[d];
        #pragma unroll
        for (int o = 8; o > 0; o >>= 1) t += __shfl_xor_sync(0x0000ffffu, t, o);
        if (d == 0) red[0] = t;
    }
    __syncthreads();
    const float mu = red[0] * (1.0f / DIN);
    __syncthreads();

    // ---- variance (two-pass, matches reference) ----
    const float dv = v - mu;
    float s2 = dv * dv;
    #pragma unroll
    for (int o = 16; o > 0; o >>= 1) s2 += __shfl_xor_sync(0xffffffffu, s2, o);
    if ((d & 31) == 0) red[d >> 5] = s2;
    __syncthreads();
    if (d < 16) {
        float t = red[d];
        #pragma unroll
        for (int o = 8; o > 0; o >>= 1) t += __shfl_xor_sync(0x0000ffffu, t, o);
        if (d == 0) red[0] = t;
    }
    __syncthreads();
    const float var = red[0] * (1.0f / DIN);
    const float xn  = dv * rsqrtf(var + 1e-5f) * gamma_[d] + beta_[d];

    // ---- cubic B-spline bases on uniform knots t_i = (i-3)*0.6 - 1.5 ----
    float b[11];
    #pragma unroll
    for (int i = 0; i < 11; i++) {
        const float t0 = (float)(i - 3) * 0.6f + (-1.5f);
        const float t1 = (float)(i - 2) * 0.6f + (-1.5f);
        b[i] = (xn >= t0 && xn < t1) ? 1.0f : 0.0f;
    }
    #pragma unroll
    for (int k = 1; k <= 3; k++) {
        #pragma unroll
        for (int i = 0; i < 11 - k; i++) {
            const float ti   = (float)(i - 3)     * 0.6f + (-1.5f);
            const float ti1  = (float)(i - 2)     * 0.6f + (-1.5f);
            const float tik  = (float)(i + k - 3) * 0.6f + (-1.5f);
            const float tik1 = (float)(i + k - 2) * 0.6f + (-1.5f);
            const float left  = (xn - ti)   * (1.0f / (tik  - ti));
            const float right = (tik1 - xn) * (1.0f / (tik1 - ti1));
            b[i] = left * b[i] + right * b[i + 1];
        }
    }

    // ---- RBF + write features ----
    float* Fp = g_F + (size_t)tok * KK + d * 9;
    Fp[0] = fmaxf(xn, 0.0f);   // ReLU channel (base branch)
    #pragma unroll
    for (int j = 0; j < NB; j++) {
        const float g = -1.5f + (float)j * (3.0f / 7.0f);
        const float u = (xn - g) * (7.0f / 3.0f);
        Fp[1 + j] = b[j] + __expf(-u * u);
    }
}

// ---------------------------------------------------------------------------
// Kernel 2: pack base_weight + spline_weight into g_W[k][o], o contiguous.
// k = d*9 + j : j==0 -> base_weight[o][d], else spline_weight[o][d*8 + j-1]
// ---------------------------------------------------------------------------
__global__ void pack_kernel(const float* __restrict__ bw,
                            const float* __restrict__ sw)
{
    const int idx = blockIdx.x * blockDim.x + threadIdx.x;
    if (idx >= KK * DOUT) return;
    const int o = idx % DOUT;
    const int k = idx / DOUT;
    const int d = k / 9;
    const int j = k % 9;
    const float v = (j == 0) ? bw[(size_t)o * DIN + d]
                             : sw[(size_t)o * (DIN * NB) + d * NB + (j - 1)];
    g_W[idx] = v;
}

// ---------------------------------------------------------------------------
// Kernel 3: SGEMM  C[16384][512] = F[16384][4608] * W[4608][512]
// 128x128 tile, BK=16, 256 threads, 8x8 microtile (4+4 split), FFMA2 inner.
// ---------------------------------------------------------------------------
__global__ __launch_bounds__(256)
void sgemm_kernel(float* __restrict__ C)
{
    __shared__ float As[2][16][132];   // [k][m], padded (132 mod 32 = 4) -> 2-way STS max
    __shared__ float Bs[2][16][128];   // [k][n]

    const float* A = g_F;
    const float* B = g_W;

    const int tid = threadIdx.x;
    const int bm  = blockIdx.y * 128;
    const int bn  = blockIdx.x * 128;

    // A tile loads: 128x16 = 512 float4; thread loads rows a_row and a_row+64
    const int a_row = tid >> 2;            // 0..63
    const int a_col = (tid & 3) << 2;      // 0,4,8,12
    const float* Ap = A + (size_t)(bm + a_row) * KK + a_col;

    // B tile loads: 16x128 = 512 float4; thread loads rows b_row and b_row+8
    const int b_row = tid >> 5;            // 0..7
    const int b_col = (tid & 31) << 2;     // 0..124
    const float* Bp = B + (size_t)b_row * 512 + bn + b_col;

    const int tx = tid & 15;               // output col group
    const int ty = tid >> 4;               // output row group

    // accumulators as packed f32x2 pairs: acc[i][jp] = (col 2jp, col 2jp+1)
    unsigned long long acc[8][4];
    #pragma unroll
    for (int i = 0; i < 8; i++)
        #pragma unroll
        for (int jp = 0; jp < 4; jp++) acc[i][jp] = 0ull;

    // prologue: stage tile 0
    float4 ra0 = *(const float4*)(Ap);
    float4 ra1 = *(const float4*)(Ap + (size_t)64 * KK);
    float4 rb0 = *(const float4*)(Bp);
    float4 rb1 = *(const float4*)(Bp + 8 * 512);

    int buf = 0;
    for (int kt = 0; kt < NKT; kt++) {
        // store staged tile into smem[buf] (A transposed)
        As[buf][a_col + 0][a_row]      = ra0.x;
        As[buf][a_col + 1][a_row]      = ra0.y;
        As[buf][a_col + 2][a_row]      = ra0.z;
        As[buf][a_col + 3][a_row]      = ra0.w;
        As[buf][a_col + 0][a_row + 64] = ra1.x;
        As[buf][a_col + 1][a_row + 64] = ra1.y;
        As[buf][a_col + 2][a_row + 64] = ra1.z;
        As[buf][a_col + 3][a_row + 64] = ra1.w;
        *(float4*)&Bs[buf][b_row][b_col]     = rb0;
        *(float4*)&Bs[buf][b_row + 8][b_col] = rb1;
        __syncthreads();

        // prefetch next tile into registers (hidden under compute)
        if (kt + 1 < NKT) {
            const float* Ap2 = Ap + (kt + 1) * 16;
            ra0 = *(const float4*)(Ap2);
            ra1 = *(const float4*)(Ap2 + (size_t)64 * KK);
            const float* Bp2 = Bp + (size_t)(kt + 1) * 16 * 512;
            rb0 = *(const float4*)(Bp2);
            rb1 = *(const float4*)(Bp2 + 8 * 512);
        }

        // compute on smem[buf]
        #pragma unroll
        for (int k = 0; k < 16; k++) {
            const float4 a0 = *(const float4*)&As[buf][k][ty * 4];
            const float4 a1 = *(const float4*)&As[buf][k][64 + ty * 4];
            const ulonglong2 bq0 = *(const ulonglong2*)&Bs[buf][k][tx * 4];
            const ulonglong2 bq1 = *(const ulonglong2*)&Bs[buf][k][64 + tx * 4];
            const unsigned long long bp0 = bq0.x, bp1 = bq0.y, bp2 = bq1.x, bp3 = bq1.y;
            const float av[8] = {a0.x, a0.y, a0.z, a0.w, a1.x, a1.y, a1.z, a1.w};
            #pragma unroll
            for (int i = 0; i < 8; i++) {
                unsigned long long ad;
                asm("mov.b64 %0, {%1, %1};" : "=l"(ad) : "f"(av[i]));
                asm("fma.rn.f32x2 %0, %1, %2, %0;" : "+l"(acc[i][0]) : "l"(ad), "l"(bp0));
                asm("fma.rn.f32x2 %0, %1, %2, %0;" : "+l"(acc[i][1]) : "l"(ad), "l"(bp1));
                asm("fma.rn.f32x2 %0, %1, %2, %0;" : "+l"(acc[i][2]) : "l"(ad), "l"(bp2));
                asm("fma.rn.f32x2 %0, %1, %2, %0;" : "+l"(acc[i][3]) : "l"(ad), "l"(bp3));
            }
        }
        buf ^= 1;
    }

    // epilogue: packed pairs already match memory order of 4 consecutive floats
    float* Cp = C + (size_t)bm * 512 + bn;
    #pragma unroll
    for (int i = 0; i < 8; i++) {
        const int r = (i < 4) ? (ty * 4 + i) : (64 + ty * 4 + (i - 4));
        ulonglong2 v0; v0.x = acc[i][0]; v0.y = acc[i][1];
        ulonglong2 v1; v1.x = acc[i][2]; v1.y = acc[i][3];
        *(ulonglong2*)&Cp[(size_t)r * 512 + tx * 4]      = v0;
        *(ulonglong2*)&Cp[(size_t)r * 512 + 64 + tx * 4] = v1;
    }
}

// ---------------------------------------------------------------------------
extern "C" void kernel_launch(void* const* d_in, const int* in_sizes, int n_in,
                              void* d_out, int out_size)
{
    const float* x  = (const float*)d_in[0];
    const float* g  = (const float*)d_in[1];
    const float* bt = (const float*)d_in[2];
    const float* bw = (const float*)d_in[3];
    const float* sw = (const float*)d_in[4];
    float* out = (float*)d_out;

    feat_kernel<<<NTOK, 512>>>(x, g, bt);
    pack_kernel<<<(KK * DOUT + 255) / 256, 256>>>(bw, sw);
    sgemm_kernel<<<dim3(4, 128), 256>>>(out);
}

// round 6
// speedup vs baseline: 2.3550x; 2.3550x over previous
#include <cuda_runtime.h>
#include <cuda_bf16.h>
#include <cstdint>

#define NTOK 16384
#define DIN  512
#define NB   8
#define KR   4608                 // real K = 512*9
#define KE   13824                // expanded K = 3*KR (split: AhBh + AlBh + AhBl)
#define BK   64                   // expanded-K per stage = 128 bytes/row
#define NST  (KE / BK)            // 216 k-stages
#define STAGE_BYTES 49152         // A 32KB + B 16KB
#define CTA_M 256
#define CTA_N 128

// Scratch (allocation-free)
__device__ __align__(16) __nv_bfloat16 g_F[(size_t)NTOK * KE];   // A expanded [tok][ke]
__device__ __align__(16) __nv_bfloat16 g_W[(size_t)512 * KE];    // B expanded [o][ke]

__device__ __forceinline__ void cpa16(uint32_t dst, const void* src) {
    asm volatile("cp.async.cg.shared.global [%0], [%1], 16;" :: "r"(dst), "l"(src));
}
__device__ __forceinline__ void ldsm_x4(uint32_t* r, uint32_t addr) {
    asm volatile("ldmatrix.sync.aligned.m8n8.x4.shared.b16 {%0,%1,%2,%3}, [%4];"
                 : "=r"(r[0]), "=r"(r[1]), "=r"(r[2]), "=r"(r[3]) : "r"(addr));
}
__device__ __forceinline__ void mma16816(float* c, const uint32_t* a,
                                         uint32_t b0, uint32_t b1) {
    asm volatile("mma.sync.aligned.m16n8k16.row.col.f32.bf16.bf16.f32 "
                 "{%0,%1,%2,%3}, {%4,%5,%6,%7}, {%8,%9}, {%0,%1,%2,%3};"
                 : "+f"(c[0]), "+f"(c[1]), "+f"(c[2]), "+f"(c[3])
                 : "r"(a[0]), "r"(a[1]), "r"(a[2]), "r"(a[3]), "r"(b0), "r"(b1));
}

// ---------------------------------------------------------------------------
// Kernel 1: LayerNorm + feature gen -> split-bf16 expanded A, coalesced writes
// ---------------------------------------------------------------------------
__global__ __launch_bounds__(512)
void feat_kernel(const float* __restrict__ x,
                 const float* __restrict__ gamma_,
                 const float* __restrict__ beta_)
{
    const int tok = blockIdx.x;
    const int d   = threadIdx.x;
    const float v = x[(size_t)tok * DIN + d];

    __shared__ float red[16];

    float s = v;
    #pragma unroll
    for (int o = 16; o > 0; o >>= 1) s += __shfl_xor_sync(0xffffffffu, s, o);
    if ((d & 31) == 0) red[d >> 5] = s;
    __syncthreads();
    if (d < 16) {
        float t = red[d];
        #pragma unroll
        for (int o = 8; o > 0; o >>= 1) t += __shfl_xor_sync(0x0000ffffu, t, o);
        if (d == 0) red[0] = t;
    }
    __syncthreads();
    const float mu = red[0] * (1.0f / DIN);
    __syncthreads();

    const float dv = v - mu;
    float s2 = dv * dv;
    #pragma unroll
    for (int o = 16; o > 0; o >>= 1) s2 += __shfl_xor_sync(0xffffffffu, s2, o);
    if ((d & 31) == 0) red[d >> 5] = s2;
    __syncthreads();
    if (d < 16) {
        float t = red[d];
        #pragma unroll
        for (int o = 8; o > 0; o >>= 1) t += __shfl_xor_sync(0x0000ffffu, t, o);
        if (d == 0) red[0] = t;
    }
    __syncthreads();
    const float var = red[0] * (1.0f / DIN);
    const float xn  = dv * rsqrtf(var + 1e-5f) * gamma_[d] + beta_[d];

    // cubic B-spline on uniform knots
    float b[11];
    #pragma unroll
    for (int i = 0; i < 11; i++) {
        const float t0 = (float)(i - 3) * 0.6f - 1.5f;
        const float t1 = (float)(i - 2) * 0.6f - 1.5f;
        b[i] = (xn >= t0 && xn < t1) ? 1.0f : 0.0f;
    }
    #pragma unroll
    for (int k = 1; k <= 3; k++) {
        #pragma unroll
        for (int i = 0; i < 11 - k; i++) {
            const float ti   = (float)(i - 3)     * 0.6f - 1.5f;
            const float ti1  = (float)(i - 2)     * 0.6f - 1.5f;
            const float tik  = (float)(i + k - 3) * 0.6f - 1.5f;
            const float tik1 = (float)(i + k - 2) * 0.6f - 1.5f;
            b[i] = (xn - ti) * (1.0f / (tik - ti)) * b[i]
                 + (tik1 - xn) * (1.0f / (tik1 - ti1)) * b[i + 1];
        }
    }

    float feat[9];
    feat[0] = fmaxf(xn, 0.0f);
    #pragma unroll
    for (int j = 0; j < NB; j++) {
        const float g = -1.5f + (float)j * (3.0f / 7.0f);
        const float u = (xn - g) * (7.0f / 3.0f);
        feat[1 + j] = b[j] + __expf(-u * u);
    }

    // region P (ke<2KR): interleaved (hi, lo) pairs; region Q: hi only
    __nv_bfloat16* row = g_F + (size_t)tok * KE;
    __nv_bfloat162* P  = reinterpret_cast<__nv_bfloat162*>(row);
    #pragma unroll
    for (int j = 0; j < 9; j++) {
        const float f = feat[j];
        const __nv_bfloat16 hi = __float2bfloat16(f);
        const __nv_bfloat16 lo = __float2bfloat16(f - __bfloat162float(hi));
        __nv_bfloat162 hl; hl.x = hi; hl.y = lo;
        P[j * 512 + d] = hl;                       // coalesced 4B stores
        row[2 * KR + j * 512 + d] = hi;            // coalesced 2B stores
    }
}

// ---------------------------------------------------------------------------
// Kernel 2: pack weights -> expanded split-bf16 B [o][ke]
//   ke < 2*KR : k = ke/2, both slots = bf16(w)   (pairs with A hi, lo)
//   ke >= 2*KR: k = ke-2*KR, slot = bf16(w - hi) (pairs with A hi)
// ---------------------------------------------------------------------------
__global__ void pack_kernel(const float* __restrict__ bw,
                            const float* __restrict__ sw)
{
    const int idx = blockIdx.x * blockDim.x + threadIdx.x;
    if (idx >= 512 * KE) return;
    const int o  = idx / KE;
    const int ke = idx % KE;
    int k; bool lo_slot;
    if (ke < 2 * KR) { k = ke >> 1;      lo_slot = false; }
    else             { k = ke - 2 * KR;  lo_slot = true;  }
    const int j = k >> 9;
    const int d = k & 511;
    const float w = (j == 0) ? bw[(size_t)o * DIN + d]
                             : sw[(size_t)o * (DIN * NB) + d * NB + (j - 1)];
    const __nv_bfloat16 hi = __float2bfloat16(w);
    g_W[idx] = lo_slot ? __float2bfloat16(w - __bfloat162float(hi)) : hi;
}

// ---------------------------------------------------------------------------
// Kernel 3: mma.sync bf16 GEMM  C[16384][512] = A_exp * B_exp^T
// CTA 256x128, 8 warps (4M x 2N) of 64x64 tiles, BK=64, SW128 smem,
// 3-stage cp.async pipeline.
// ---------------------------------------------------------------------------
__global__ __launch_bounds__(256, 1)
void gemm_kernel(float* __restrict__ C)
{
    extern __shared__ char smem_raw[];
    uint32_t raw;
    asm("{ .reg .u64 t; cvta.to.shared.u64 t, %1; cvt.u32.u64 %0, t; }"
        : "=r"(raw) : "l"(smem_raw));
    const uint32_t base = (raw + 1023) & ~1023u;

    const int tid  = threadIdx.x;
    const int wid  = tid >> 5;
    const int lane = tid & 31;
    const int wm   = wid & 3;          // 0..3 along M (64 each)
    const int wn   = wid >> 2;         // 0..1 along N (64 each)
    const int bm   = blockIdx.y * CTA_M;
    const int bn   = blockIdx.x * CTA_N;

    // loader mapping: lane group of 8 covers one 128B row; rows stride 32
    const int ld_r0 = tid >> 3;        // 0..31
    const int ld_c  = tid & 7;         // 16B chunk 0..7

    float acc[4][8][4];
    #pragma unroll
    for (int mt = 0; mt < 4; mt++)
        #pragma unroll
        for (int nt = 0; nt < 8; nt++)
            #pragma unroll
            for (int q = 0; q < 4; q++) acc[mt][nt][q] = 0.0f;

    auto load_stage = [&](int s) {
        const uint32_t SA = base + (s % 3) * STAGE_BYTES;
        const uint32_t SB = SA + 32768;
        const int ko = s * BK;
        #pragma unroll
        for (int i = 0; i < 8; i++) {            // A: 256 rows
            const int r = ld_r0 + i * 32;
            cpa16(SA + r * 128 + ((ld_c ^ (r & 7)) << 4),
                  g_F + (size_t)(bm + r) * KE + ko + ld_c * 8);
        }
        #pragma unroll
        for (int i = 0; i < 4; i++) {            // B: 128 rows
            const int r = ld_r0 + i * 32;
            cpa16(SB + r * 128 + ((ld_c ^ (r & 7)) << 4),
                  g_W + (size_t)(bn + r) * KE + ko + ld_c * 8);
        }
    };

    // prologue
    load_stage(0); asm volatile("cp.async.commit_group;" ::: "memory");
    load_stage(1); asm volatile("cp.async.commit_group;" ::: "memory");

    for (int s = 0; s < NST; s++) {
        asm volatile("cp.async.wait_group 1;" ::: "memory");
        __syncthreads();

        if (s + 2 < NST) load_stage(s + 2);
        asm volatile("cp.async.commit_group;" ::: "memory");

        const uint32_t SA = base + (s % 3) * STAGE_BYTES;
        const uint32_t SB = SA + 32768;

        #pragma unroll
        for (int ks = 0; ks < 4; ks++) {
            uint32_t a[4][4], b[4][4];
            // A frags: 4 m-tiles of m16k16
            #pragma unroll
            for (int mt = 0; mt < 4; mt++) {
                const int r = wm * 64 + mt * 16 + (lane & 15);
                const int c = ks * 2 + (lane >> 4);
                ldsm_x4(a[mt], SA + r * 128 + ((c ^ (r & 7)) << 4));
            }
            // B frags: 4 pairs of n-tiles (each x4 = b0,b1 for nt=2p and 2p+1)
            #pragma unroll
            for (int p = 0; p < 4; p++) {
                const int r = wn * 64 + p * 16 + (lane & 7) + ((lane >> 4) << 3);
                const int c = ks * 2 + ((lane >> 3) & 1);
                ldsm_x4(b[p], SB + r * 128 + ((c ^ (r & 7)) << 4));
            }
            #pragma unroll
            for (int mt = 0; mt < 4; mt++)
                #pragma unroll
                for (int nt = 0; nt < 8; nt++) {
                    const uint32_t b0 = (nt & 1) ? b[nt >> 1][2] : b[nt >> 1][0];
                    const uint32_t b1 = (nt & 1) ? b[nt >> 1][3] : b[nt >> 1][1];
                    mma16816(acc[mt][nt], a[mt], b0, b1);
                }
        }
    }

    // epilogue: thread t holds rows g, g+8; cols 2tg, 2tg+1 per (mt, nt)
    const int g  = lane >> 2;
    const int tg = lane & 3;
    #pragma unroll
    for (int mt = 0; mt < 4; mt++) {
        const int row0 = bm + wm * 64 + mt * 16 + g;
        #pragma unroll
        for (int nt = 0; nt < 8; nt++) {
            const int col = bn + wn * 64 + nt * 8 + tg * 2;
            float2 v0; v0.x = acc[mt][nt][0]; v0.y = acc[mt][nt][1];
            float2 v1; v1.x = acc[mt][nt][2]; v1.y = acc[mt][nt][3];
            *(float2*)&C[(size_t)row0 * 512 + col]       = v0;
            *(float2*)&C[(size_t)(row0 + 8) * 512 + col] = v1;
        }
    }
}

// ---------------------------------------------------------------------------
extern "C" void kernel_launch(void* const* d_in, const int* in_sizes, int n_in,
                              void* d_out, int out_size)
{
    const float* x  = (const float*)d_in[0];
    const float* g  = (const float*)d_in[1];
    const float* bt = (const float*)d_in[2];
    const float* bw = (const float*)d_in[3];
    const float* sw = (const float*)d_in[4];
    float* out = (float*)d_out;

    const int SMEM_DYN = 1024 + 3 * STAGE_BYTES;   // align slack + 3 stages
    cudaFuncSetAttribute(gemm_kernel, cudaFuncAttributeMaxDynamicSharedMemorySize, SMEM_DYN);

    feat_kernel<<<NTOK, 512>>>(x, g, bt);
    pack_kernel<<<(512 * KE + 255) / 256, 256>>>(bw, sw);
    gemm_kernel<<<dim3(512 / CTA_N, NTOK / CTA_M), 256, SMEM_DYN>>>(out);
}

// round 7
// speedup vs baseline: 2.7612x; 1.1725x over previous
#include <cuda_runtime.h>
#include <cuda_bf16.h>
#include <cstdint>

#define NTOK 16384
#define DIN  512
#define NB   8
#define KR   4608                 // real K = 512*9
#define KE   13824                // expanded K = 3*KR (split: AhBh + AlBh + AhBl)
#define BK   64                   // expanded-K per stage = 128 bytes/row
#define NST  (KE / BK)            // 216 k-stages (divisible by 4)
#define STAGE_BYTES 49152         // A 32KB + B 16KB
#define CTA_M 256
#define CTA_N 128

// Scratch (allocation-free)
__device__ __align__(16) __nv_bfloat16 g_F[(size_t)NTOK * KE];   // A expanded [tok][ke]
__device__ __align__(16) __nv_bfloat16 g_W[(size_t)512 * KE];    // B expanded [o][ke]

__device__ __forceinline__ void cpa16(uint32_t dst, const void* src) {
    asm volatile("cp.async.cg.shared.global [%0], [%1], 16;" :: "r"(dst), "l"(src));
}
__device__ __forceinline__ void ldsm_x4(uint32_t* r, uint32_t addr) {
    asm volatile("ldmatrix.sync.aligned.m8n8.x4.shared.b16 {%0,%1,%2,%3}, [%4];"
                 : "=r"(r[0]), "=r"(r[1]), "=r"(r[2]), "=r"(r[3]) : "r"(addr));
}
__device__ __forceinline__ void mma16816(float* c, const uint32_t* a,
                                         uint32_t b0, uint32_t b1) {
    asm volatile("mma.sync.aligned.m16n8k16.row.col.f32.bf16.bf16.f32 "
                 "{%0,%1,%2,%3}, {%4,%5,%6,%7}, {%8,%9}, {%0,%1,%2,%3};"
                 : "+f"(c[0]), "+f"(c[1]), "+f"(c[2]), "+f"(c[3])
                 : "r"(a[0]), "r"(a[1]), "r"(a[2]), "r"(a[3]), "r"(b0), "r"(b1));
}

// ---------------------------------------------------------------------------
// Kernel 1: LayerNorm + feature gen -> split-bf16 expanded A, coalesced writes
// ---------------------------------------------------------------------------
__global__ __launch_bounds__(512)
void feat_kernel(const float* __restrict__ x,
                 const float* __restrict__ gamma_,
                 const float* __restrict__ beta_)
{
    const int tok = blockIdx.x;
    const int d   = threadIdx.x;
    const float v = x[(size_t)tok * DIN + d];

    __shared__ float red1[16], red2[16];

    // single-pass sum / sumsq reduction
    float s1 = v, s2 = v * v;
    #pragma unroll
    for (int o = 16; o > 0; o >>= 1) {
        s1 += __shfl_xor_sync(0xffffffffu, s1, o);
        s2 += __shfl_xor_sync(0xffffffffu, s2, o);
    }
    if ((d & 31) == 0) { red1[d >> 5] = s1; red2[d >> 5] = s2; }
    __syncthreads();
    if (d < 16) {
        float t1 = red1[d], t2 = red2[d];
        #pragma unroll
        for (int o = 8; o > 0; o >>= 1) {
            t1 += __shfl_xor_sync(0x0000ffffu, t1, o);
            t2 += __shfl_xor_sync(0x0000ffffu, t2, o);
        }
        if (d == 0) { red1[0] = t1; red2[0] = t2; }
    }
    __syncthreads();
    const float mu  = red1[0] * (1.0f / DIN);
    const float var = red2[0] * (1.0f / DIN) - mu * mu;
    const float xn  = (v - mu) * rsqrtf(var + 1e-5f) * gamma_[d] + beta_[d];

    // cubic B-spline on uniform knots
    float b[11];
    #pragma unroll
    for (int i = 0; i < 11; i++) {
        const float t0 = (float)(i - 3) * 0.6f - 1.5f;
        const float t1 = (float)(i - 2) * 0.6f - 1.5f;
        b[i] = (xn >= t0 && xn < t1) ? 1.0f : 0.0f;
    }
    #pragma unroll
    for (int k = 1; k <= 3; k++) {
        #pragma unroll
        for (int i = 0; i < 11 - k; i++) {
            const float ti   = (float)(i - 3)     * 0.6f - 1.5f;
            const float ti1  = (float)(i - 2)     * 0.6f - 1.5f;
            const float tik  = (float)(i + k - 3) * 0.6f - 1.5f;
            const float tik1 = (float)(i + k - 2) * 0.6f - 1.5f;
            b[i] = (xn - ti) * (1.0f / (tik - ti)) * b[i]
                 + (tik1 - xn) * (1.0f / (tik1 - ti1)) * b[i + 1];
        }
    }

    float feat[9];
    feat[0] = fmaxf(xn, 0.0f);
    #pragma unroll
    for (int j = 0; j < NB; j++) {
        const float g = -1.5f + (float)j * (3.0f / 7.0f);
        const float u = (xn - g) * (7.0f / 3.0f);
        feat[1 + j] = b[j] + __expf(-u * u);
    }

    // region P (ke<2KR): interleaved (hi, lo) pairs; region Q: hi only
    __nv_bfloat16* row = g_F + (size_t)tok * KE;
    __nv_bfloat162* P  = reinterpret_cast<__nv_bfloat162*>(row);
    #pragma unroll
    for (int j = 0; j < 9; j++) {
        const float f = feat[j];
        const __nv_bfloat16 hi = __float2bfloat16(f);
        const __nv_bfloat16 lo = __float2bfloat16(f - __bfloat162float(hi));
        __nv_bfloat162 hl; hl.x = hi; hl.y = lo;
        P[j * 512 + d] = hl;                       // coalesced 4B stores
        row[2 * KR + j * 512 + d] = hi;            // coalesced 2B stores
    }
}

// ---------------------------------------------------------------------------
// Kernel 2: pack weights -> expanded split-bf16 B [o][ke]
// ---------------------------------------------------------------------------
__global__ void pack_kernel(const float* __restrict__ bw,
                            const float* __restrict__ sw)
{
    const int idx = blockIdx.x * blockDim.x + threadIdx.x;
    if (idx >= 512 * KE) return;
    const int o  = idx / KE;
    const int ke = idx % KE;
    int k; bool lo_slot;
    if (ke < 2 * KR) { k = ke >> 1;      lo_slot = false; }
    else             { k = ke - 2 * KR;  lo_slot = true;  }
    const int j = k >> 9;
    const int d = k & 511;
    const float w = (j == 0) ? bw[(size_t)o * DIN + d]
                             : sw[(size_t)o * (DIN * NB) + d * NB + (j - 1)];
    const __nv_bfloat16 hi = __float2bfloat16(w);
    g_W[idx] = lo_slot ? __float2bfloat16(w - __bfloat162float(hi)) : hi;
}

// ---------------------------------------------------------------------------
// Kernel 3: mma.sync bf16 GEMM  C[16384][512] = A_exp * B_exp^T
// CTA 256x128, 8 warps (4M x 2N) of 64x64 tiles, BK=64, SW128 smem,
// 4-stage cp.async pipeline (static bases via x4 unroll), frag double-buffer.
// ---------------------------------------------------------------------------
__global__ __launch_bounds__(256, 1)
void gemm_kernel(float* __restrict__ C)
{
    extern __shared__ char smem_raw[];
    uint32_t raw;
    asm("{ .reg .u64 t; cvta.to.shared.u64 t, %1; cvt.u32.u64 %0, t; }"
        : "=r"(raw) : "l"(smem_raw));
    const uint32_t base = (raw + 1023) & ~1023u;

    const int tid  = threadIdx.x;
    const int wid  = tid >> 5;
    const int lane = tid & 31;
    const int wm   = wid & 3;          // 0..3 along M (64 each)
    const int wn   = wid >> 2;         // 0..1 along N (64 each)
    const int bm   = blockIdx.y * CTA_M;
    const int bn   = blockIdx.x * CTA_N;

    // loader mapping
    const int ld_r0 = tid >> 3;        // 0..31
    const int ld_c  = tid & 7;         // 16B chunk

    // frag address invariants (row offsets are multiples of 8 -> r&7 == lane&7)
    const int rx  = lane & 7;
    const int hiA = lane >> 4;          // 0/1 -> k8 half for A
    const int hiB = (lane >> 3) & 1;    // 0/1 -> k8 half for B
    uint32_t aoff[4], boff[4];
    #pragma unroll
    for (int mt = 0; mt < 4; mt++)
        aoff[mt] = (uint32_t)(wm * 64 + mt * 16 + (lane & 15)) * 128u;
    #pragma unroll
    for (int p = 0; p < 4; p++)
        boff[p] = 32768u + (uint32_t)(wn * 64 + p * 16 + (lane & 7) + ((lane >> 4) << 3)) * 128u;

    float acc[4][8][4];
    #pragma unroll
    for (int mt = 0; mt < 4; mt++)
        #pragma unroll
        for (int nt = 0; nt < 8; nt++)
            #pragma unroll
            for (int q = 0; q < 4; q++) acc[mt][nt][q] = 0.0f;

    uint32_t fa[2][4][4], fb[2][4][4];

    #define LOAD_STAGE(sidx, SBASE) do {                                        \
        const int ko_ = (sidx) * BK;                                            \
        _Pragma("unroll")                                                       \
        for (int i_ = 0; i_ < 8; i_++) {                                        \
            const int r_ = ld_r0 + i_ * 32;                                     \
            cpa16((SBASE) + r_ * 128 + ((ld_c ^ (r_ & 7)) << 4),                \
                  g_F + (size_t)(bm + r_) * KE + ko_ + ld_c * 8);               \
        }                                                                       \
        _Pragma("unroll")                                                       \
        for (int i_ = 0; i_ < 4; i_++) {                                        \
            const int r_ = ld_r0 + i_ * 32;                                     \
            cpa16((SBASE) + 32768u + r_ * 128 + ((ld_c ^ (r_ & 7)) << 4),       \
                  g_W + (size_t)(bn + r_) * KE + ko_ + ld_c * 8);               \
        }                                                                       \
    } while (0)

    #define LOAD_FRAGS(SBASE, ks_, A_, B_) do {                                 \
        _Pragma("unroll")                                                       \
        for (int mt_ = 0; mt_ < 4; mt_++)                                       \
            ldsm_x4((A_)[mt_], (SBASE) + aoff[mt_] +                            \
                    ((uint32_t)((((ks_) << 1) | hiA) ^ rx) << 4));              \
        _Pragma("unroll")                                                       \
        for (int p_ = 0; p_ < 4; p_++)                                          \
            ldsm_x4((B_)[p_], (SBASE) + boff[p_] +                              \
                    ((uint32_t)((((ks_) << 1) | hiB) ^ rx) << 4));              \
    } while (0)

    #define MMA_ALL(A_, B_) do {                                                \
        _Pragma("unroll")                                                       \
        for (int mt_ = 0; mt_ < 4; mt_++)                                       \
            _Pragma("unroll")                                                   \
            for (int nt_ = 0; nt_ < 8; nt_++) {                                 \
                const uint32_t b0_ = (nt_ & 1) ? (B_)[nt_ >> 1][2] : (B_)[nt_ >> 1][0]; \
                const uint32_t b1_ = (nt_ & 1) ? (B_)[nt_ >> 1][3] : (B_)[nt_ >> 1][1]; \
                mma16816(acc[mt_][nt_], (A_)[mt_], b0_, b1_);                   \
            }                                                                   \
    } while (0)

    #define STEP(sv, BUF) do {                                                  \
        const int s_ = (sv);                                                    \
        asm volatile("cp.async.wait_group 2;" ::: "memory");                    \
        __syncthreads();                                                        \
        const uint32_t SA_ = base + (uint32_t)(BUF) * STAGE_BYTES;              \
        LOAD_FRAGS(SA_, 0, fa[0], fb[0]);                                       \
        if (s_ + 3 < NST) {                                                     \
            const uint32_t SN_ = base + (uint32_t)(((BUF) + 3) & 3) * STAGE_BYTES; \
            LOAD_STAGE(s_ + 3, SN_);                                            \
        }                                                                       \
        asm volatile("cp.async.commit_group;" ::: "memory");                    \
        _Pragma("unroll")                                                       \
        for (int ks_ = 0; ks_ < 4; ks_++) {                                     \
            const int cur_ = ks_ & 1;                                           \
            if (ks_ < 3) LOAD_FRAGS(SA_, ks_ + 1, fa[cur_ ^ 1], fb[cur_ ^ 1]);  \
            MMA_ALL(fa[cur_], fb[cur_]);                                        \
        }                                                                       \
    } while (0)

    // prologue: stages 0..2 into bufs 0..2
    LOAD_STAGE(0, base);
    asm volatile("cp.async.commit_group;" ::: "memory");
    LOAD_STAGE(1, base + STAGE_BYTES);
    asm volatile("cp.async.commit_group;" ::: "memory");
    LOAD_STAGE(2, base + 2 * STAGE_BYTES);
    asm volatile("cp.async.commit_group;" ::: "memory");

    for (int t = 0; t < NST; t += 4) {
        STEP(t + 0, 0);
        STEP(t + 1, 1);
        STEP(t + 2, 2);
        STEP(t + 3, 3);
    }

    // epilogue: thread holds rows g, g+8; cols 2tg, 2tg+1 per (mt, nt)
    const int g  = lane >> 2;
    const int tg = lane & 3;
    #pragma unroll
    for (int mt = 0; mt < 4; mt++) {
        const int row0 = bm + wm * 64 + mt * 16 + g;
        #pragma unroll
        for (int nt = 0; nt < 8; nt++) {
            const int col = bn + wn * 64 + nt * 8 + tg * 2;
            float2 v0; v0.x = acc[mt][nt][0]; v0.y = acc[mt][nt][1];
            float2 v1; v1.x = acc[mt][nt][2]; v1.y = acc[mt][nt][3];
            *(float2*)&C[(size_t)row0 * 512 + col]       = v0;
            *(float2*)&C[(size_t)(row0 + 8) * 512 + col] = v1;
        }
    }
}

// ---------------------------------------------------------------------------
extern "C" void kernel_launch(void* const* d_in, const int* in_sizes, int n_in,
                              void* d_out, int out_size)
{
    const float* x  = (const float*)d_in[0];
    const float* g  = (const float*)d_in[1];
    const float* bt = (const float*)d_in[2];
    const float* bw = (const float*)d_in[3];
    const float* sw = (const float*)d_in[4];
    float* out = (float*)d_out;

    const int SMEM_DYN = 1024 + 4 * STAGE_BYTES;   // align slack + 4 stages = 197632
    cudaFuncSetAttribute(gemm_kernel, cudaFuncAttributeMaxDynamicSharedMemorySize, SMEM_DYN);

    feat_kernel<<<NTOK, 512>>>(x, g, bt);
    pack_kernel<<<(512 * KE + 255) / 256, 256>>>(bw, sw);
    gemm_kernel<<<dim3(512 / CTA_N, NTOK / CTA_M), 256, SMEM_DYN>>>(out);
}